// round 13
// baseline (speedup 1.0000x reference)
#include <cuda_runtime.h>
#include <cuda_fp16.h>
#include <math.h>
#include <stdint.h>

#define NN 50000
#define FF 64
#define HH 32
#define TT 8
#define EE 800000
#define PP 800000
#define MTOT (TT * NN)          // 400000 scan elements
#define SBLKS 1563              // ceil(MTOT/256)

// ---------------- scratch (device globals) ----------------------------------
__device__ int      g_deg[MTOT];
__device__ int      g_cnt[MTOT];
__device__ float    g_dis[MTOT];
__device__ int      g_start[MTOT];
__device__ int      g_cursor[MTOT];
__device__ int      g_bsum[SBLKS];
__device__ int      g_bpre[SBLKS];
__device__ uint32_t g_csrp[TT * EE];      // src(17b) | bf16(dis[src]) sans sign (15b)

__device__ __align__(16) uint8_t  g_INf8[NN * 96];   // [x (64) | H (32)] e4m3 rows
__device__ __align__(16) uint8_t  g_OUT1f8[NN * 96];
__device__ __align__(16) uint8_t  g_OUT2f8[NN * 96];
__device__ float    g_C[NN * HH];         // cell state stays fp32
__device__ __align__(16) uint32_t g_Wcath[144 * 128]; // f16x2 pairs, PERMUTED cols
__device__ float    g_bias[128];          // unpermuted: g*32+h
__device__ __align__(16) uint32_t g_h1h[NN * 8];      // h1 as f16x2 (32-B rows)

__device__ __forceinline__ float sigmoidf_(float x) {
    return 1.f / (1.f + expf(-x));
}

__device__ __forceinline__ uint16_t enc_e4m3x2(float hi, float lo) {
    uint16_t r;
    asm("cvt.rn.satfinite.e4m3x2.f32 %0, %1, %2;" : "=h"(r) : "f"(hi), "f"(lo));
    return r;
}

// unified gate weight row k (0..287), gate g, channel h
__device__ __forceinline__ float wrow(int k, int g, int h,
                                      const float* __restrict__ Wx,
                                      const float* __restrict__ Wh) {
    if (k < 64)  return Wx[((g * 3 + 0) * 64 + k) * 32 + h]
                      - Wx[((g * 3 + 2) * 64 + k) * 32 + h];
    if (k < 96)  return Wh[((g * 3 + 0) * 32 + (k - 64)) * 32 + h]
                      - Wh[((g * 3 + 2) * 32 + (k - 64)) * 32 + h];
    if (k < 160) return Wx[((g * 3 + 1) * 64 + (k - 96)) * 32 + h];
    if (k < 192) return Wh[((g * 3 + 1) * 32 + (k - 160)) * 32 + h];
    if (k < 256) return 2.f * Wx[((g * 3 + 2) * 64 + (k - 192)) * 32 + h];
    return 2.f * Wh[((g * 3 + 2) * 32 + (k - 256)) * 32 + h];
}

// ---------------- fused setup ------------------------------------------------
__global__ __launch_bounds__(256) void setup_kernel(
        const float* __restrict__ x,
        const float* __restrict__ Wx, const float* __restrict__ bx,
        const float* __restrict__ Wh, const float* __restrict__ bh,
        const float* __restrict__ bg) {
    const int W1 = 144 * 128;                 // packed f16 weights
    const int B1 = W1 + 128;                  // bias
    const int R1 = B1 + NN * 16;              // x -> fp8 packs (16 u32/node)
    const int R2 = R1 + NN * 8;               // zero H (8 u32/node)
    const int R3 = R2 + NN * 8;               // zero C float4
    const int R4 = R3 + MTOT;                 // zero deg+cnt
    int i = blockIdx.x * blockDim.x + threadIdx.x;
    int stride = gridDim.x * blockDim.x;
    for (int j = i; j < R4; j += stride) {
        if (j < W1) {
            int ku = j >> 7, no = j & 127;
            int g = (no & 1) | (((no >> 3) & 1) << 1);
            int h = ((no >> 1) & 3) | (((no >> 4) & 7) << 2);
            float v0 = wrow(2 * ku, g, h, Wx, Wh);
            float v1 = wrow(2 * ku + 1, g, h, Wx, Wh);
            __half2 p = __floats2half2_rn(v0, v1);
            g_Wcath[j] = *(uint32_t*)&p;
        } else if (j < B1) {
            int o = j - W1;
            int g = o >> 5, h = o & 31;
            g_bias[o] = bx[g * 32 + h] + bh[g * 32 + h] + bg[g * 32 + h];
        } else if (j < R1) {
            int q = j - B1;
            int n = q >> 4, c = q & 15;
            float4 v = ((const float4*)x)[q];
            uint16_t a = enc_e4m3x2(v.y, v.x);
            uint16_t b = enc_e4m3x2(v.w, v.z);
            ((uint32_t*)g_INf8)[n * 24 + c] = ((uint32_t)b << 16) | a;
        } else if (j < R2) {
            int q = j - R1;
            int n = q >> 3, c = q & 7;
            ((uint32_t*)g_INf8)[n * 24 + 16 + c] = 0u;
        } else if (j < R3) {
            int q = j - R2;
            ((float4*)g_C)[q] = make_float4(0.f, 0.f, 0.f, 0.f);
        } else {
            int q = j - R3;
            g_deg[q] = 0;
            g_cnt[q] = 0;
        }
    }
}

// ---------------- batched CSR build (all 8 timesteps) ------------------------
__global__ __launch_bounds__(256) void count_all(const int* __restrict__ ei) {
    int e = blockIdx.x * blockDim.x + threadIdx.x;
    if (e < TT * EE) {
        int t = e / EE;
        int k = e - t * EE;
        const int* base = ei + (size_t)t * 2 * EE;
        atomicAdd(&g_deg[t * NN + base[k]], 1);
        atomicAdd(&g_cnt[t * NN + base[EE + k]], 1);
    }
}

__global__ __launch_bounds__(256) void scan1_kernel() {
    __shared__ int s[256];
    int tid = threadIdx.x;
    int i = blockIdx.x * 256 + tid;
    s[tid] = (i < MTOT) ? g_cnt[i] : 0;
    __syncthreads();
    for (int off = 128; off > 0; off >>= 1) {
        if (tid < off) s[tid] += s[tid + off];
        __syncthreads();
    }
    if (tid == 0) g_bsum[blockIdx.x] = s[0];
}

__global__ __launch_bounds__(256) void scan2_kernel() {
    __shared__ int s[256];
    const int CH = (SBLKS + 255) / 256;   // 7
    int tid = threadIdx.x;
    int sum = 0;
    for (int k = 0; k < CH; k++) {
        int idx = tid * CH + k;
        if (idx < SBLKS) sum += g_bsum[idx];
    }
    s[tid] = sum;
    __syncthreads();
    for (int off = 1; off < 256; off <<= 1) {
        int v = (tid >= off) ? s[tid - off] : 0;
        __syncthreads();
        s[tid] += v;
        __syncthreads();
    }
    int run = (tid > 0) ? s[tid - 1] : 0;
    for (int k = 0; k < CH; k++) {
        int idx = tid * CH + k;
        if (idx < SBLKS) {
            g_bpre[idx] = run;
            run += g_bsum[idx];
        }
    }
}

__global__ __launch_bounds__(256) void scan3_kernel() {
    __shared__ int s[256];
    int tid = threadIdx.x;
    int i = blockIdx.x * 256 + tid;
    int c = (i < MTOT) ? g_cnt[i] : 0;
    s[tid] = c;
    __syncthreads();
    for (int off = 1; off < 256; off <<= 1) {
        int v = (tid >= off) ? s[tid - off] : 0;
        __syncthreads();
        s[tid] += v;
        __syncthreads();
    }
    if (i < MTOT) {
        int st = g_bpre[blockIdx.x] + s[tid] - c;
        g_start[i] = st;
        g_cursor[i] = st;
        int d = g_deg[i];
        g_dis[i] = (d > 0) ? rsqrtf((float)d) : 0.f;
    }
}

__global__ __launch_bounds__(256) void scatter_all(const int* __restrict__ ei) {
    int e = blockIdx.x * blockDim.x + threadIdx.x;
    if (e < TT * EE) {
        int t = e / EE;
        int k = e - t * EE;
        const int* base = ei + (size_t)t * 2 * EE;
        int r = base[k];
        int c = base[EE + k];
        float w = g_dis[t * NN + r];
        uint32_t u = __float_as_uint(w);
        uint32_t bf = (u + 0x8000u) >> 16;      // round-to-nearest bf16, sign=0
        uint32_t packed = (bf << 17) | (uint32_t)r;
        int pos = atomicAdd(&g_cursor[t * NN + c], 1);
        g_csrp[pos] = packed;
    }
}

// ---------------- gather (fp8 96-B rows): out[n] = -dis[n]*sum w_e*in[src] --
// one warp per node; lanes 0..23 own one u32 (4 fp8) of the 96 features
__global__ __launch_bounds__(256) void gather_kernel(int t, int pass) {
    const uint8_t* in = pass ? g_OUT1f8 : g_INf8;
    uint8_t* out      = pass ? g_OUT2f8 : g_OUT1f8;
    int gtid = blockIdx.x * blockDim.x + threadIdx.x;
    int n = gtid >> 5;
    int lane = gtid & 31;
    if (n >= NN) return;
    int base = t * NN + n;
    int c = (lane < 24) ? lane : 0;
    float2 acc0 = make_float2(0.f, 0.f);
    float2 acc1 = make_float2(0.f, 0.f);
    int s = g_start[base];
    int e2 = s + g_cnt[base];

#define EDGE_ACC(P) do {                                                      \
        uint32_t p_ = (P);                                                    \
        int r_ = p_ & 0x1FFFF;                                                \
        float w_ = __uint_as_float((p_ >> 17) << 16);                         \
        uint32_t v_ = ((const uint32_t*)(in + (size_t)r_ * 96))[c];           \
        uint32_t lo_, hi_;                                                    \
        asm("cvt.rn.f16x2.e4m3x2 %0, %1;" : "=r"(lo_) : "h"((uint16_t)(v_ & 0xFFFFu))); \
        asm("cvt.rn.f16x2.e4m3x2 %0, %1;" : "=r"(hi_) : "h"((uint16_t)(v_ >> 16)));     \
        float2 f0_ = __half22float2(*(__half2*)&lo_);                         \
        float2 f1_ = __half22float2(*(__half2*)&hi_);                         \
        acc0.x += w_ * f0_.x; acc0.y += w_ * f0_.y;                           \
        acc1.x += w_ * f1_.x; acc1.y += w_ * f1_.y;                           \
    } while (0)

    int j = s;
    for (; j + 3 < e2; j += 4) {
        uint32_t p0 = g_csrp[j];
        uint32_t p1 = g_csrp[j + 1];
        uint32_t p2 = g_csrp[j + 2];
        uint32_t p3 = g_csrp[j + 3];
        EDGE_ACC(p0); EDGE_ACC(p1); EDGE_ACC(p2); EDGE_ACC(p3);
    }
    for (; j < e2; j++) EDGE_ACC(g_csrp[j]);
#undef EDGE_ACC

    float dn = -g_dis[base];
    if (lane < 24) {
        uint16_t a = enc_e4m3x2(dn * acc0.y, dn * acc0.x);
        uint16_t b = enc_e4m3x2(dn * acc1.y, dn * acc1.x);
        ((uint32_t*)(out + (size_t)n * 96))[c] = ((uint32_t)b << 16) | a;
    }
}

// ---------------- f16 tensor-core gate GEMM + LSTM (128 nodes/block) --------
// GATES[128n x 128o] per block via mma.sync.m16n8k16.f16 (K=288, 9 chunks).
// 8 warps: mw = warp&3 (16-node M tiles x2 halves), nw = warp>>2 (64-col half).
__global__ __launch_bounds__(256) void gates_kernel(const float* __restrict__ wc) {
    __shared__ uint32_t sIn[128 * 20];   // [node][ku f16x2], stride 20
    __shared__ uint32_t sW[128 * 20];    // [col][ku f16x2],  stride 20
    int tid = threadIdx.x;
    int lane = tid & 31;
    int w = tid >> 5;
    int mw = w & 3;
    int nw = w >> 2;
    int nb = blockIdx.x * 128;
    int r = lane >> 2;
    int l = lane & 3;

    float acc[2][8][4];
#pragma unroll
    for (int mh = 0; mh < 2; mh++)
#pragma unroll
        for (int nt = 0; nt < 8; nt++)
#pragma unroll
            for (int q = 0; q < 4; q++) acc[mh][nt][q] = 0.f;

    for (int cc = 0; cc < 9; cc++) {
        const uint8_t* src8 = (cc < 3) ? g_INf8 : (cc < 6) ? g_OUT1f8 : g_OUT2f8;
        int off = (cc - (cc < 3 ? 0 : cc < 6 ? 3 : 6)) * 32;   // byte offset in row
        // A tile: 128 nodes x 8 fp8-u32 -> 16 f16x2
#pragma unroll
        for (int i = 0; i < 4; i++) {
            int lin = i * 256 + tid;
            int nl = lin >> 3, ku = lin & 7;
            int n = nb + nl;
            uint32_t v = (n < NN)
                ? ((const uint32_t*)(src8 + (size_t)n * 96 + off))[ku] : 0u;
            uint32_t lo, hi;
            asm("cvt.rn.f16x2.e4m3x2 %0, %1;" : "=r"(lo) : "h"((uint16_t)(v & 0xFFFFu)));
            asm("cvt.rn.f16x2.e4m3x2 %0, %1;" : "=r"(hi) : "h"((uint16_t)(v >> 16)));
            sIn[nl * 20 + 2 * ku] = lo;
            sIn[nl * 20 + 2 * ku + 1] = hi;
        }
        // B tile: 128 cols x 16 u32 (f16x2)
#pragma unroll
        for (int i = 0; i < 8; i++) {
            int lin = i * 256 + tid;
            int col = lin & 127, kl = lin >> 7;
            sW[col * 20 + kl] = g_Wcath[(size_t)(cc * 16 + kl) * 128 + col];
        }
        __syncthreads();
#pragma unroll
        for (int ks = 0; ks < 2; ks++) {
            int k0 = ks * 8;
            uint32_t a[2][4];
#pragma unroll
            for (int mh = 0; mh < 2; mh++) {
                int mrow = mh * 64 + mw * 16;
                a[mh][0] = sIn[(mrow + r) * 20 + k0 + l];
                a[mh][1] = sIn[(mrow + r + 8) * 20 + k0 + l];
                a[mh][2] = sIn[(mrow + r) * 20 + k0 + l + 4];
                a[mh][3] = sIn[(mrow + r + 8) * 20 + k0 + l + 4];
            }
#pragma unroll
            for (int nt = 0; nt < 8; nt++) {
                int n0 = nw * 64 + nt * 8;
                uint32_t b0 = sW[(n0 + r) * 20 + k0 + l];
                uint32_t b1 = sW[(n0 + r) * 20 + k0 + l + 4];
#pragma unroll
                for (int mh = 0; mh < 2; mh++) {
                    asm volatile(
                        "mma.sync.aligned.m16n8k16.row.col.f32.f16.f16.f32 "
                        "{%0,%1,%2,%3}, {%4,%5,%6,%7}, {%8,%9}, {%0,%1,%2,%3};"
                        : "+f"(acc[mh][nt][0]), "+f"(acc[mh][nt][1]),
                          "+f"(acc[mh][nt][2]), "+f"(acc[mh][nt][3])
                        : "r"(a[mh][0]), "r"(a[mh][1]), "r"(a[mh][2]), "r"(a[mh][3]),
                          "r"(b0), "r"(b1));
                }
            }
        }
        __syncthreads();
    }

    // epilogue: per mh, thread owns nodes {n0, n0+8} x channels ch (all 4 gates)
#pragma unroll
    for (int mh = 0; mh < 2; mh++) {
        int nbase = nb + mh * 64 + mw * 16 + r;
#pragma unroll
        for (int p = 0; p < 4; p++) {
            int ch = (nw * 4 + p) * 4 + l;
            float bi = g_bias[ch], bf = g_bias[32 + ch];
            float bc = g_bias[64 + ch], bo = g_bias[96 + ch];
            float wci = wc[ch], wcf = wc[32 + ch], wco = wc[64 + ch];
#pragma unroll
            for (int half = 0; half < 2; half++) {
                int n = nbase + half * 8;
                if (n < NN) {
                    float pi = acc[mh][2 * p][half * 2 + 0] + bi;
                    float pf = acc[mh][2 * p][half * 2 + 1] + bf;
                    float pc = acc[mh][2 * p + 1][half * 2 + 0] + bc;
                    float po = acc[mh][2 * p + 1][half * 2 + 1] + bo;
                    float cs = g_C[(size_t)n * 32 + ch];
                    float ig = sigmoidf_(pi + wci * cs);
                    float fg = sigmoidf_(pf + wcf * cs);
                    float cn = fg * cs + ig * tanhf(pc);
                    float og = sigmoidf_(po + wco * cn);
                    g_C[(size_t)n * 32 + ch] = cn;
                    uint16_t hh = enc_e4m3x2(0.f, og * tanhf(cn));
                    g_INf8[(size_t)n * 96 + 64 + ch] = (uint8_t)(hh & 0xFF);
                }
            }
        }
    }
}

// ---------------- head: h1 = relu(relu(H) @ fc1 + b1) -> f16 ----------------
__global__ __launch_bounds__(256) void h1_kernel(const float* __restrict__ w,
                                                 const float* __restrict__ b) {
    __shared__ float sw[32 * 16];
    __shared__ float sb[16];
    int tid = threadIdx.x;
    for (int i = tid; i < 512; i += blockDim.x) sw[i] = w[i];
    if (tid < 16) sb[tid] = b[tid];
    __syncthreads();
    int n = blockIdx.x * blockDim.x + tid;
    if (n >= NN) return;
    float h[32];
    const uint32_t* hp = (const uint32_t*)(g_INf8 + (size_t)n * 96 + 64);
#pragma unroll
    for (int ku = 0; ku < 8; ku++) {
        uint32_t v = hp[ku];
        uint32_t lo, hi;
        asm("cvt.rn.f16x2.e4m3x2 %0, %1;" : "=r"(lo) : "h"((uint16_t)(v & 0xFFFFu)));
        asm("cvt.rn.f16x2.e4m3x2 %0, %1;" : "=r"(hi) : "h"((uint16_t)(v >> 16)));
        float2 f0 = __half22float2(*(__half2*)&lo);
        float2 f1 = __half22float2(*(__half2*)&hi);
        h[4 * ku + 0] = fmaxf(f0.x, 0.f);
        h[4 * ku + 1] = fmaxf(f0.y, 0.f);
        h[4 * ku + 2] = fmaxf(f1.x, 0.f);
        h[4 * ku + 3] = fmaxf(f1.y, 0.f);
    }
#pragma unroll
    for (int o = 0; o < 8; o++) {
        float a0 = sb[2 * o], a1 = sb[2 * o + 1];
#pragma unroll
        for (int k = 0; k < 32; k++) {
            a0 += h[k] * sw[k * 16 + 2 * o];
            a1 += h[k] * sw[k * 16 + 2 * o + 1];
        }
        __half2 p = __floats2half2_rn(fmaxf(a0, 0.f), fmaxf(a1, 0.f));
        g_h1h[(size_t)n * 8 + o] = *(uint32_t*)&p;
    }
}

// ---------------- head: pair MLP (h1 in f16) ---------------------------------
__global__ __launch_bounds__(256) void pair_kernel(
        const int* __restrict__ src, const int* __restrict__ dst,
        const float* __restrict__ w2, const float* __restrict__ b2,
        const float* __restrict__ w3, const float* __restrict__ b3,
        const float* __restrict__ wb, const float* __restrict__ bb,
        float* __restrict__ out) {
    __shared__ float s2[512], s3[128], sb2[16], sb3[8], swb[8];
    __shared__ float sbb;
    int tid = threadIdx.x;
    for (int i = tid; i < 512; i += 256) s2[i] = w2[i];
    for (int i = tid; i < 128; i += 256) s3[i] = w3[i];
    if (tid < 16) sb2[tid] = b2[tid];
    if (tid < 8) { sb3[tid] = b3[tid]; swb[tid] = wb[tid]; }
    if (tid == 0) sbb = bb[0];
    __syncthreads();
    int p = blockIdx.x * 256 + tid;
    if (p >= PP) return;
    int s = src[p], d = dst[p];
    float z[32];
    const uint4* hs = (const uint4*)(g_h1h + (size_t)s * 8);
    const uint4* hd = (const uint4*)(g_h1h + (size_t)d * 8);
#pragma unroll
    for (int q = 0; q < 2; q++) {
        uint4 v = hs[q];
        float2 f0 = __half22float2(*(__half2*)&v.x);
        float2 f1 = __half22float2(*(__half2*)&v.y);
        float2 f2 = __half22float2(*(__half2*)&v.z);
        float2 f3 = __half22float2(*(__half2*)&v.w);
        z[q * 8 + 0] = f0.x; z[q * 8 + 1] = f0.y;
        z[q * 8 + 2] = f1.x; z[q * 8 + 3] = f1.y;
        z[q * 8 + 4] = f2.x; z[q * 8 + 5] = f2.y;
        z[q * 8 + 6] = f3.x; z[q * 8 + 7] = f3.y;
    }
#pragma unroll
    for (int q = 0; q < 2; q++) {
        uint4 v = hd[q];
        float2 f0 = __half22float2(*(__half2*)&v.x);
        float2 f1 = __half22float2(*(__half2*)&v.y);
        float2 f2 = __half22float2(*(__half2*)&v.z);
        float2 f3 = __half22float2(*(__half2*)&v.w);
        z[16 + q * 8 + 0] = f0.x; z[16 + q * 8 + 1] = f0.y;
        z[16 + q * 8 + 2] = f1.x; z[16 + q * 8 + 3] = f1.y;
        z[16 + q * 8 + 4] = f2.x; z[16 + q * 8 + 5] = f2.y;
        z[16 + q * 8 + 6] = f3.x; z[16 + q * 8 + 7] = f3.y;
    }
    float h2[16];
#pragma unroll
    for (int o = 0; o < 16; o++) {
        float acc = sb2[o];
#pragma unroll
        for (int k = 0; k < 32; k++) acc += z[k] * s2[k * 16 + o];
        h2[o] = fmaxf(acc, 0.f);
    }
    float h3[8];
#pragma unroll
    for (int o = 0; o < 8; o++) {
        float acc = sb3[o];
#pragma unroll
        for (int k = 0; k < 16; k++) acc += h2[k] * s3[k * 8 + o];
        h3[o] = fmaxf(acc, 0.f);
    }
    float acc = sbb;
#pragma unroll
    for (int k = 0; k < 8; k++) acc += h3[k] * swb[k];
    out[p] = sigmoidf_(acc);
}

// ---------------- launch ----------------------------------------------------
extern "C" void kernel_launch(void* const* d_in, const int* in_sizes, int n_in,
                              void* d_out, int out_size) {
    const float* x    = (const float*)d_in[0];
    const int*   ei   = (const int*)d_in[1];
    const int*   src  = (const int*)d_in[2];
    const int*   dst  = (const int*)d_in[3];
    const float* Wx   = (const float*)d_in[4];
    const float* bx   = (const float*)d_in[5];
    const float* Wh   = (const float*)d_in[6];
    const float* bh   = (const float*)d_in[7];
    const float* bg   = (const float*)d_in[8];
    const float* wc   = (const float*)d_in[9];
    const float* fc1w = (const float*)d_in[10];
    const float* fc1b = (const float*)d_in[11];
    const float* fc2w = (const float*)d_in[12];
    const float* fc2b = (const float*)d_in[13];
    const float* fc3w = (const float*)d_in[14];
    const float* fc3b = (const float*)d_in[15];
    const float* bfcw = (const float*)d_in[16];
    const float* bfcb = (const float*)d_in[17];
    float* out = (float*)d_out;

    setup_kernel<<<2048, 256>>>(x, Wx, bx, Wh, bh, bg);
    count_all<<<(TT * EE + 255) / 256, 256>>>(ei);
    scan1_kernel<<<SBLKS, 256>>>();
    scan2_kernel<<<1, 256>>>();
    scan3_kernel<<<SBLKS, 256>>>();
    scatter_all<<<(TT * EE + 255) / 256, 256>>>(ei);

    for (int t = 0; t < TT; t++) {
        gather_kernel<<<(NN * 32 + 255) / 256, 256>>>(t, 0);
        gather_kernel<<<(NN * 32 + 255) / 256, 256>>>(t, 1);
        gates_kernel<<<(NN + 127) / 128, 256>>>(wc);
    }

    h1_kernel<<<(NN + 255) / 256, 256>>>(fc1w, fc1b);
    pair_kernel<<<(PP + 255) / 256, 256>>>(src, dst, fc2w, fc2b, fc3w, fc3b, bfcw, bfcb, out);
}

// round 14
// speedup vs baseline: 1.0959x; 1.0959x over previous
#include <cuda_runtime.h>
#include <cuda_fp16.h>
#include <math.h>
#include <stdint.h>

#define NN 50000
#define FF 64
#define HH 32
#define TT 8
#define EE 800000
#define PP 800000
#define MTOT (TT * NN)          // 400000 scan elements
#define SBLKS 1563              // ceil(MTOT/256)

// ---------------- scratch (device globals) ----------------------------------
__device__ int      g_deg[MTOT];
__device__ int      g_cnt[MTOT];
__device__ float    g_dis[MTOT];
__device__ int      g_start[MTOT];
__device__ int      g_cursor[MTOT];
__device__ int      g_bsum[SBLKS];
__device__ int      g_bpre[SBLKS];
__device__ uint32_t g_csrp[TT * EE];      // src(17b) | bf16(dis[src]) sans sign (15b)

__device__ __align__(16) uint8_t  g_INf8[NN * 96];   // [x (64) | H (32)] e4m3 rows
__device__ __align__(16) uint8_t  g_OUT1f8[NN * 96];
__device__ __align__(16) uint8_t  g_OUT2f8[NN * 96];
__device__ float    g_C[NN * HH];         // cell state stays fp32
__device__ __align__(16) uint32_t g_Wcath[144 * 128]; // f16x2 pairs, PERMUTED cols
__device__ float    g_bias[128];          // unpermuted: g*32+h
__device__ __align__(16) uint32_t g_h1h[NN * 8];      // h1 as f16x2 (32-B rows)

__device__ __forceinline__ float sigmoidf_(float x) {
    return 1.f / (1.f + expf(-x));
}

__device__ __forceinline__ uint16_t enc_e4m3x2(float hi, float lo) {
    uint16_t r;
    asm("cvt.rn.satfinite.e4m3x2.f32 %0, %1, %2;" : "=h"(r) : "f"(hi), "f"(lo));
    return r;
}

// unified gate weight row k (0..287), gate g, channel h
__device__ __forceinline__ float wrow(int k, int g, int h,
                                      const float* __restrict__ Wx,
                                      const float* __restrict__ Wh) {
    if (k < 64)  return Wx[((g * 3 + 0) * 64 + k) * 32 + h]
                      - Wx[((g * 3 + 2) * 64 + k) * 32 + h];
    if (k < 96)  return Wh[((g * 3 + 0) * 32 + (k - 64)) * 32 + h]
                      - Wh[((g * 3 + 2) * 32 + (k - 64)) * 32 + h];
    if (k < 160) return Wx[((g * 3 + 1) * 64 + (k - 96)) * 32 + h];
    if (k < 192) return Wh[((g * 3 + 1) * 32 + (k - 160)) * 32 + h];
    if (k < 256) return 2.f * Wx[((g * 3 + 2) * 64 + (k - 192)) * 32 + h];
    return 2.f * Wh[((g * 3 + 2) * 32 + (k - 256)) * 32 + h];
}

// ---------------- fused setup ------------------------------------------------
__global__ __launch_bounds__(256) void setup_kernel(
        const float* __restrict__ x,
        const float* __restrict__ Wx, const float* __restrict__ bx,
        const float* __restrict__ Wh, const float* __restrict__ bh,
        const float* __restrict__ bg) {
    const int W1 = 144 * 128;                 // packed f16 weights
    const int B1 = W1 + 128;                  // bias
    const int R1 = B1 + NN * 16;              // x -> fp8 packs (16 u32/node)
    const int R2 = R1 + NN * 8;               // zero H (8 u32/node)
    const int R3 = R2 + NN * 8;               // zero C float4
    const int R4 = R3 + MTOT;                 // zero deg+cnt
    int i = blockIdx.x * blockDim.x + threadIdx.x;
    int stride = gridDim.x * blockDim.x;
    for (int j = i; j < R4; j += stride) {
        if (j < W1) {
            int ku = j >> 7, no = j & 127;
            int g = (no & 1) | (((no >> 3) & 1) << 1);
            int h = ((no >> 1) & 3) | (((no >> 4) & 7) << 2);
            float v0 = wrow(2 * ku, g, h, Wx, Wh);
            float v1 = wrow(2 * ku + 1, g, h, Wx, Wh);
            __half2 p = __floats2half2_rn(v0, v1);
            g_Wcath[j] = *(uint32_t*)&p;
        } else if (j < B1) {
            int o = j - W1;
            int g = o >> 5, h = o & 31;
            g_bias[o] = bx[g * 32 + h] + bh[g * 32 + h] + bg[g * 32 + h];
        } else if (j < R1) {
            int q = j - B1;
            int n = q >> 4, c = q & 15;
            float4 v = ((const float4*)x)[q];
            uint16_t a = enc_e4m3x2(v.y, v.x);
            uint16_t b = enc_e4m3x2(v.w, v.z);
            ((uint32_t*)g_INf8)[n * 24 + c] = ((uint32_t)b << 16) | a;
        } else if (j < R2) {
            int q = j - R1;
            int n = q >> 3, c = q & 7;
            ((uint32_t*)g_INf8)[n * 24 + 16 + c] = 0u;
        } else if (j < R3) {
            int q = j - R2;
            ((float4*)g_C)[q] = make_float4(0.f, 0.f, 0.f, 0.f);
        } else {
            int q = j - R3;
            g_deg[q] = 0;
            g_cnt[q] = 0;
        }
    }
}

// ---------------- batched CSR build (all 8 timesteps) ------------------------
__global__ __launch_bounds__(256) void count_all(const int* __restrict__ ei) {
    int e = blockIdx.x * blockDim.x + threadIdx.x;
    if (e < TT * EE) {
        int t = e / EE;
        int k = e - t * EE;
        const int* base = ei + (size_t)t * 2 * EE;
        atomicAdd(&g_deg[t * NN + base[k]], 1);
        atomicAdd(&g_cnt[t * NN + base[EE + k]], 1);
    }
}

__global__ __launch_bounds__(256) void scan1_kernel() {
    __shared__ int s[256];
    int tid = threadIdx.x;
    int i = blockIdx.x * 256 + tid;
    s[tid] = (i < MTOT) ? g_cnt[i] : 0;
    __syncthreads();
    for (int off = 128; off > 0; off >>= 1) {
        if (tid < off) s[tid] += s[tid + off];
        __syncthreads();
    }
    if (tid == 0) g_bsum[blockIdx.x] = s[0];
}

__global__ __launch_bounds__(256) void scan2_kernel() {
    __shared__ int s[256];
    const int CH = (SBLKS + 255) / 256;   // 7
    int tid = threadIdx.x;
    int sum = 0;
    for (int k = 0; k < CH; k++) {
        int idx = tid * CH + k;
        if (idx < SBLKS) sum += g_bsum[idx];
    }
    s[tid] = sum;
    __syncthreads();
    for (int off = 1; off < 256; off <<= 1) {
        int v = (tid >= off) ? s[tid - off] : 0;
        __syncthreads();
        s[tid] += v;
        __syncthreads();
    }
    int run = (tid > 0) ? s[tid - 1] : 0;
    for (int k = 0; k < CH; k++) {
        int idx = tid * CH + k;
        if (idx < SBLKS) {
            g_bpre[idx] = run;
            run += g_bsum[idx];
        }
    }
}

__global__ __launch_bounds__(256) void scan3_kernel() {
    __shared__ int s[256];
    int tid = threadIdx.x;
    int i = blockIdx.x * 256 + tid;
    int c = (i < MTOT) ? g_cnt[i] : 0;
    s[tid] = c;
    __syncthreads();
    for (int off = 1; off < 256; off <<= 1) {
        int v = (tid >= off) ? s[tid - off] : 0;
        __syncthreads();
        s[tid] += v;
        __syncthreads();
    }
    if (i < MTOT) {
        int st = g_bpre[blockIdx.x] + s[tid] - c;
        g_start[i] = st;
        g_cursor[i] = st;
        int d = g_deg[i];
        g_dis[i] = (d > 0) ? rsqrtf((float)d) : 0.f;
    }
}

__global__ __launch_bounds__(256) void scatter_all(const int* __restrict__ ei) {
    int e = blockIdx.x * blockDim.x + threadIdx.x;
    if (e < TT * EE) {
        int t = e / EE;
        int k = e - t * EE;
        const int* base = ei + (size_t)t * 2 * EE;
        int r = base[k];
        int c = base[EE + k];
        float w = g_dis[t * NN + r];
        uint32_t u = __float_as_uint(w);
        uint32_t bf = (u + 0x8000u) >> 16;      // round-to-nearest bf16, sign=0
        uint32_t packed = (bf << 17) | (uint32_t)r;
        int pos = atomicAdd(&g_cursor[t * NN + c], 1);
        g_csrp[pos] = packed;
    }
}

// ---------------- gather (fp8 96-B rows): out[n] = -dis[n]*sum w_e*in[src] --
// one warp per node; lanes 0..23 own one u32 (4 fp8) of the 96 features
__global__ __launch_bounds__(256) void gather_kernel(int t, int pass) {
    const uint8_t* in = pass ? g_OUT1f8 : g_INf8;
    uint8_t* out      = pass ? g_OUT2f8 : g_OUT1f8;
    int gtid = blockIdx.x * blockDim.x + threadIdx.x;
    int n = gtid >> 5;
    int lane = gtid & 31;
    if (n >= NN) return;
    int base = t * NN + n;
    int c = (lane < 24) ? lane : 0;
    float2 acc0 = make_float2(0.f, 0.f);
    float2 acc1 = make_float2(0.f, 0.f);
    int s = g_start[base];
    int e2 = s + g_cnt[base];

#define EDGE_ACC(P) do {                                                      \
        uint32_t p_ = (P);                                                    \
        int r_ = p_ & 0x1FFFF;                                                \
        float w_ = __uint_as_float((p_ >> 17) << 16);                         \
        uint32_t v_ = ((const uint32_t*)(in + (size_t)r_ * 96))[c];           \
        uint32_t lo_, hi_;                                                    \
        asm("cvt.rn.f16x2.e4m3x2 %0, %1;" : "=r"(lo_) : "h"((uint16_t)(v_ & 0xFFFFu))); \
        asm("cvt.rn.f16x2.e4m3x2 %0, %1;" : "=r"(hi_) : "h"((uint16_t)(v_ >> 16)));     \
        float2 f0_ = __half22float2(*(__half2*)&lo_);                         \
        float2 f1_ = __half22float2(*(__half2*)&hi_);                         \
        acc0.x += w_ * f0_.x; acc0.y += w_ * f0_.y;                           \
        acc1.x += w_ * f1_.x; acc1.y += w_ * f1_.y;                           \
    } while (0)

    int j = s;
    for (; j + 7 < e2; j += 8) {
        uint32_t p0 = g_csrp[j];
        uint32_t p1 = g_csrp[j + 1];
        uint32_t p2 = g_csrp[j + 2];
        uint32_t p3 = g_csrp[j + 3];
        uint32_t p4 = g_csrp[j + 4];
        uint32_t p5 = g_csrp[j + 5];
        uint32_t p6 = g_csrp[j + 6];
        uint32_t p7 = g_csrp[j + 7];
        EDGE_ACC(p0); EDGE_ACC(p1); EDGE_ACC(p2); EDGE_ACC(p3);
        EDGE_ACC(p4); EDGE_ACC(p5); EDGE_ACC(p6); EDGE_ACC(p7);
    }
    for (; j + 3 < e2; j += 4) {
        uint32_t p0 = g_csrp[j];
        uint32_t p1 = g_csrp[j + 1];
        uint32_t p2 = g_csrp[j + 2];
        uint32_t p3 = g_csrp[j + 3];
        EDGE_ACC(p0); EDGE_ACC(p1); EDGE_ACC(p2); EDGE_ACC(p3);
    }
    for (; j < e2; j++) EDGE_ACC(g_csrp[j]);
#undef EDGE_ACC

    float dn = -g_dis[base];
    if (lane < 24) {
        uint16_t a = enc_e4m3x2(dn * acc0.y, dn * acc0.x);
        uint16_t b = enc_e4m3x2(dn * acc1.y, dn * acc1.x);
        ((uint32_t*)(out + (size_t)n * 96))[c] = ((uint32_t)b << 16) | a;
    }
}

// ---------------- f16 tensor-core gate GEMM + LSTM (64 nodes/block, R8) -----
// GATES[64n x 128o] per block via mma.sync.m16n8k16.f16 (K=288, 9 chunks).
// 8 warps: mw = warp&3 (16-node M tile), nw = warp>>2 (64-col N half).
__global__ __launch_bounds__(256) void gates_kernel(const float* __restrict__ wc) {
    __shared__ uint32_t sIn[64 * 20];    // [node][ku f16x2], stride 20
    __shared__ uint32_t sW[128 * 20];    // [col][ku f16x2],  stride 20
    int tid = threadIdx.x;
    int lane = tid & 31;
    int w = tid >> 5;
    int mw = w & 3;
    int nw = w >> 2;
    int nb = blockIdx.x * 64;
    int r = lane >> 2;       // fragment row within 8
    int l = lane & 3;        // fragment k-pair group

    float acc[8][4];
#pragma unroll
    for (int nt = 0; nt < 8; nt++)
#pragma unroll
        for (int q = 0; q < 4; q++) acc[nt][q] = 0.f;

    for (int cc = 0; cc < 9; cc++) {
        const uint8_t* src8 = (cc < 3) ? g_INf8 : (cc < 6) ? g_OUT1f8 : g_OUT2f8;
        int off = (cc - (cc < 3 ? 0 : cc < 6 ? 3 : 6)) * 32;   // byte offset
        // A tile: 64 nodes x 8 u32 of fp8 -> decode to 16 u32 of f16x2
#pragma unroll
        for (int i = 0; i < 2; i++) {
            int lin = i * 256 + tid;
            int nl = lin >> 3, ku = lin & 7;
            int n = nb + nl;
            uint32_t v = (n < NN)
                ? ((const uint32_t*)(src8 + (size_t)n * 96 + off))[ku] : 0u;
            uint32_t lo, hi;
            asm("cvt.rn.f16x2.e4m3x2 %0, %1;" : "=r"(lo) : "h"((uint16_t)(v & 0xFFFFu)));
            asm("cvt.rn.f16x2.e4m3x2 %0, %1;" : "=r"(hi) : "h"((uint16_t)(v >> 16)));
            sIn[nl * 20 + 2 * ku] = lo;
            sIn[nl * 20 + 2 * ku + 1] = hi;
        }
        // B tile: 128 cols x 16 u32 (f16x2)
#pragma unroll
        for (int i = 0; i < 8; i++) {
            int lin = i * 256 + tid;
            int col = lin & 127, kl = lin >> 7;
            sW[col * 20 + kl] = g_Wcath[(size_t)(cc * 16 + kl) * 128 + col];
        }
        __syncthreads();
#pragma unroll
        for (int ks = 0; ks < 2; ks++) {
            int k0 = ks * 8;
            uint32_t a0 = sIn[(mw * 16 + r) * 20 + k0 + l];
            uint32_t a1 = sIn[(mw * 16 + r + 8) * 20 + k0 + l];
            uint32_t a2 = sIn[(mw * 16 + r) * 20 + k0 + l + 4];
            uint32_t a3 = sIn[(mw * 16 + r + 8) * 20 + k0 + l + 4];
#pragma unroll
            for (int nt = 0; nt < 8; nt++) {
                int n0 = nw * 64 + nt * 8;
                uint32_t b0 = sW[(n0 + r) * 20 + k0 + l];
                uint32_t b1 = sW[(n0 + r) * 20 + k0 + l + 4];
                asm volatile(
                    "mma.sync.aligned.m16n8k16.row.col.f32.f16.f16.f32 "
                    "{%0,%1,%2,%3}, {%4,%5,%6,%7}, {%8,%9}, {%0,%1,%2,%3};"
                    : "+f"(acc[nt][0]), "+f"(acc[nt][1]),
                      "+f"(acc[nt][2]), "+f"(acc[nt][3])
                    : "r"(a0), "r"(a1), "r"(a2), "r"(a3), "r"(b0), "r"(b1));
            }
        }
        __syncthreads();
    }

    // epilogue: thread owns nodes {n0, n0+8} x channels ch=16nw+4p+l (all 4 gates)
    int n0 = nb + mw * 16 + r;
    int n1 = n0 + 8;
#pragma unroll
    for (int p = 0; p < 4; p++) {
        int ch = (nw * 4 + p) * 4 + l;
        float bi = g_bias[ch], bf = g_bias[32 + ch];
        float bc = g_bias[64 + ch], bo = g_bias[96 + ch];
        float wci = wc[ch], wcf = wc[32 + ch], wco = wc[64 + ch];
#pragma unroll
        for (int half = 0; half < 2; half++) {
            int n = half ? n1 : n0;
            if (n < NN) {
                float pi = acc[2 * p][half * 2 + 0] + bi;
                float pf = acc[2 * p][half * 2 + 1] + bf;
                float pc = acc[2 * p + 1][half * 2 + 0] + bc;
                float po = acc[2 * p + 1][half * 2 + 1] + bo;
                float cs = g_C[(size_t)n * 32 + ch];
                float ig = sigmoidf_(pi + wci * cs);
                float fg = sigmoidf_(pf + wcf * cs);
                float cn = fg * cs + ig * tanhf(pc);
                float og = sigmoidf_(po + wco * cn);
                g_C[(size_t)n * 32 + ch] = cn;
                uint16_t hh = enc_e4m3x2(0.f, og * tanhf(cn));
                g_INf8[(size_t)n * 96 + 64 + ch] = (uint8_t)(hh & 0xFF);
            }
        }
    }
}

// ---------------- head: h1 = relu(relu(H) @ fc1 + b1) -> f16 ----------------
__global__ __launch_bounds__(256) void h1_kernel(const float* __restrict__ w,
                                                 const float* __restrict__ b) {
    __shared__ float sw[32 * 16];
    __shared__ float sb[16];
    int tid = threadIdx.x;
    for (int i = tid; i < 512; i += blockDim.x) sw[i] = w[i];
    if (tid < 16) sb[tid] = b[tid];
    __syncthreads();
    int n = blockIdx.x * blockDim.x + tid;
    if (n >= NN) return;
    float h[32];
    const uint32_t* hp = (const uint32_t*)(g_INf8 + (size_t)n * 96 + 64);
#pragma unroll
    for (int ku = 0; ku < 8; ku++) {
        uint32_t v = hp[ku];
        uint32_t lo, hi;
        asm("cvt.rn.f16x2.e4m3x2 %0, %1;" : "=r"(lo) : "h"((uint16_t)(v & 0xFFFFu)));
        asm("cvt.rn.f16x2.e4m3x2 %0, %1;" : "=r"(hi) : "h"((uint16_t)(v >> 16)));
        float2 f0 = __half22float2(*(__half2*)&lo);
        float2 f1 = __half22float2(*(__half2*)&hi);
        h[4 * ku + 0] = fmaxf(f0.x, 0.f);
        h[4 * ku + 1] = fmaxf(f0.y, 0.f);
        h[4 * ku + 2] = fmaxf(f1.x, 0.f);
        h[4 * ku + 3] = fmaxf(f1.y, 0.f);
    }
#pragma unroll
    for (int o = 0; o < 8; o++) {
        float a0 = sb[2 * o], a1 = sb[2 * o + 1];
#pragma unroll
        for (int k = 0; k < 32; k++) {
            a0 += h[k] * sw[k * 16 + 2 * o];
            a1 += h[k] * sw[k * 16 + 2 * o + 1];
        }
        __half2 p = __floats2half2_rn(fmaxf(a0, 0.f), fmaxf(a1, 0.f));
        g_h1h[(size_t)n * 8 + o] = *(uint32_t*)&p;
    }
}

// ---------------- head: pair MLP (h1 in f16) ---------------------------------
__global__ __launch_bounds__(256) void pair_kernel(
        const int* __restrict__ src, const int* __restrict__ dst,
        const float* __restrict__ w2, const float* __restrict__ b2,
        const float* __restrict__ w3, const float* __restrict__ b3,
        const float* __restrict__ wb, const float* __restrict__ bb,
        float* __restrict__ out) {
    __shared__ float s2[512], s3[128], sb2[16], sb3[8], swb[8];
    __shared__ float sbb;
    int tid = threadIdx.x;
    for (int i = tid; i < 512; i += 256) s2[i] = w2[i];
    for (int i = tid; i < 128; i += 256) s3[i] = w3[i];
    if (tid < 16) sb2[tid] = b2[tid];
    if (tid < 8) { sb3[tid] = b3[tid]; swb[tid] = wb[tid]; }
    if (tid == 0) sbb = bb[0];
    __syncthreads();
    int p = blockIdx.x * 256 + tid;
    if (p >= PP) return;
    int s = src[p], d = dst[p];
    float z[32];
    const uint4* hs = (const uint4*)(g_h1h + (size_t)s * 8);
    const uint4* hd = (const uint4*)(g_h1h + (size_t)d * 8);
#pragma unroll
    for (int q = 0; q < 2; q++) {
        uint4 v = hs[q];
        float2 f0 = __half22float2(*(__half2*)&v.x);
        float2 f1 = __half22float2(*(__half2*)&v.y);
        float2 f2 = __half22float2(*(__half2*)&v.z);
        float2 f3 = __half22float2(*(__half2*)&v.w);
        z[q * 8 + 0] = f0.x; z[q * 8 + 1] = f0.y;
        z[q * 8 + 2] = f1.x; z[q * 8 + 3] = f1.y;
        z[q * 8 + 4] = f2.x; z[q * 8 + 5] = f2.y;
        z[q * 8 + 6] = f3.x; z[q * 8 + 7] = f3.y;
    }
#pragma unroll
    for (int q = 0; q < 2; q++) {
        uint4 v = hd[q];
        float2 f0 = __half22float2(*(__half2*)&v.x);
        float2 f1 = __half22float2(*(__half2*)&v.y);
        float2 f2 = __half22float2(*(__half2*)&v.z);
        float2 f3 = __half22float2(*(__half2*)&v.w);
        z[16 + q * 8 + 0] = f0.x; z[16 + q * 8 + 1] = f0.y;
        z[16 + q * 8 + 2] = f1.x; z[16 + q * 8 + 3] = f1.y;
        z[16 + q * 8 + 4] = f2.x; z[16 + q * 8 + 5] = f2.y;
        z[16 + q * 8 + 6] = f3.x; z[16 + q * 8 + 7] = f3.y;
    }
    float h2[16];
#pragma unroll
    for (int o = 0; o < 16; o++) {
        float acc = sb2[o];
#pragma unroll
        for (int k = 0; k < 32; k++) acc += z[k] * s2[k * 16 + o];
        h2[o] = fmaxf(acc, 0.f);
    }
    float h3[8];
#pragma unroll
    for (int o = 0; o < 8; o++) {
        float acc = sb3[o];
#pragma unroll
        for (int k = 0; k < 16; k++) acc += h2[k] * s3[k * 8 + o];
        h3[o] = fmaxf(acc, 0.f);
    }
    float acc = sbb;
#pragma unroll
    for (int k = 0; k < 8; k++) acc += h3[k] * swb[k];
    out[p] = sigmoidf_(acc);
}

// ---------------- launch ----------------------------------------------------
extern "C" void kernel_launch(void* const* d_in, const int* in_sizes, int n_in,
                              void* d_out, int out_size) {
    const float* x    = (const float*)d_in[0];
    const int*   ei   = (const int*)d_in[1];
    const int*   src  = (const int*)d_in[2];
    const int*   dst  = (const int*)d_in[3];
    const float* Wx   = (const float*)d_in[4];
    const float* bx   = (const float*)d_in[5];
    const float* Wh   = (const float*)d_in[6];
    const float* bh   = (const float*)d_in[7];
    const float* bg   = (const float*)d_in[8];
    const float* wc   = (const float*)d_in[9];
    const float* fc1w = (const float*)d_in[10];
    const float* fc1b = (const float*)d_in[11];
    const float* fc2w = (const float*)d_in[12];
    const float* fc2b = (const float*)d_in[13];
    const float* fc3w = (const float*)d_in[14];
    const float* fc3b = (const float*)d_in[15];
    const float* bfcw = (const float*)d_in[16];
    const float* bfcb = (const float*)d_in[17];
    float* out = (float*)d_out;

    setup_kernel<<<2048, 256>>>(x, Wx, bx, Wh, bh, bg);
    count_all<<<(TT * EE + 255) / 256, 256>>>(ei);
    scan1_kernel<<<SBLKS, 256>>>();
    scan2_kernel<<<1, 256>>>();
    scan3_kernel<<<SBLKS, 256>>>();
    scatter_all<<<(TT * EE + 255) / 256, 256>>>(ei);

    for (int t = 0; t < TT; t++) {
        gather_kernel<<<(NN * 32 + 255) / 256, 256>>>(t, 0);
        gather_kernel<<<(NN * 32 + 255) / 256, 256>>>(t, 1);
        gates_kernel<<<(NN + 63) / 64, 256>>>(wc);
    }

    h1_kernel<<<(NN + 255) / 256, 256>>>(fc1w, fc1b);
    pair_kernel<<<(PP + 255) / 256, 256>>>(src, dst, fc2w, fc2b, fc3w, fc3b, bfcw, bfcb, out);
}